// round 9
// baseline (speedup 1.0000x reference)
#include <cuda_runtime.h>
#include <math.h>

// ---------------------------------------------------------------------------
// DCTModel collapsed to a single kernel:
//   out[b, cq*54+m(u,v), i, j] =
//     sum_{r,s<3} W[i][u][r] * W[j][v][s] * t[b,cq, base_i+r, base_j+s]
//   t = 127.5 * (RGB2YCBCR @ x);  additive constants only hit the dropped DC.
//
// R7/R8: all 3 cq channels fused into one block (grid 1344 -> 448). Weight
// construction (27% of block instructions) now runs once instead of 3x;
// the YCbCr tile holds 3 planes (same input LDG traffic: 3 loads -> 3 combos
// -> 3 STS per element). Consumer loops cq=0..2 over the unchanged
// contraction + float2-store epilogue.
// (R8 = R7 resubmitted verbatim: R8's bench was an infra failure, no data.)
// ---------------------------------------------------------------------------

#define HW 112
#define NPLANE 12544
#define NBATCH 16

#define BX 56           // j-pairs per block
#define BY 4            // i rows per block
#define NTHREADS (BX*BY)
#define ROWS_T 6
#define COLS_T 114
#define PLANE_T (ROWS_T*COLS_T)   // 684
#define PSTRIDE 68      // floats per pair in sW4 (64 data + 4 pad)

__constant__ float c_M[3][3] = {
    { 0.299f,     0.587f,    0.114f    },
    {-0.168736f, -0.331264f, 0.5f      },
    { 0.5f,      -0.418688f, -0.081312f}
};

// SUB_CHANNELS = {0,1,2,3,4,5,8,9,16,24}
#define SUB_MASK 0x000000000101033FULL

// ---------------------------------------------------------------------------
// cos(k*pi/16), constexpr -> folded to FFMA immediates in unrolled loops.
// ---------------------------------------------------------------------------
__host__ __device__ constexpr float cosw(int k) {
    const double T[9] = {
        1.0,
        0.98078528040323044913,
        0.92387953251128675613,
        0.83146961230254523708,
        0.70710678118654752440,
        0.55557023301960222474,
        0.38268343236508977173,
        0.19509032201612826785,
        0.0
    };
    k &= 31;
    if (k > 16) k = 32 - k;
    double s = 1.0;
    if (k > 8) { s = -1.0; k = 16 - k; }
    return (float)(s * T[k]);
}

// base index: src is monotone in x, so base = i0[x=0]
__device__ __forceinline__ int comp_base(int idx) {
    float src = (float)(8 * idx * 111) / 895.0f;
    int f = (int)floorf(src);
    return (f > HW - 2) ? (HW - 2) : f;
}

// Fused (DCT x upsample) weights for one block index: W[v][k], k<3.
__device__ __forceinline__ void comp_weights(int idx, float W[8][3]) {
    const int base = comp_base(idx);
    float A0[8], A1[8], A2[8];
    #pragma unroll
    for (int x = 0; x < 8; x++) {
        float src = (float)((8 * idx + x) * 111) / 895.0f;
        int f = (int)floorf(src);
        if (f > HW - 2) f = HW - 2;
        float w = src - (float)f;
        bool z = (f == base);           // offset 0 or 1
        A0[x] = z ? 1.0f - w : 0.0f;
        A1[x] = z ? w        : 1.0f - w;
        A2[x] = z ? 0.0f     : w;
    }
    #pragma unroll
    for (int v = 0; v < 8; v++) {
        float s0 = 0.f, s1 = 0.f, s2 = 0.f;
        #pragma unroll
        for (int x = 0; x < 8; x++) {
            const float c = cosw((2 * x + 1) * v);   // compile-time immediate
            s0 = fmaf(c, A0[x], s0);
            s1 = fmaf(c, A1[x], s1);
            s2 = fmaf(c, A2[x], s2);
        }
        const float sc = (v == 0) ? 0.35355339059327373f : 0.5f;  // alpha_v/2
        W[v][0] = s0 * sc; W[v][1] = s1 * sc; W[v][2] = s2 * sc;
    }
}

// ---------------------------------------------------------------------------
// Single kernel: block = (56 j-pairs, 4 i-rows); grid = (28, 1, 16 b).
// Each block covers all 3 cq channels.
// ---------------------------------------------------------------------------
__global__ __launch_bounds__(NTHREADS, 4)
void dct_main_kernel(const float* __restrict__ x, float* __restrict__ out) {
    __shared__ __align__(16) float sW4[BX * PSTRIDE]; // 15.2 KB
    __shared__ float sR[BY * 25];                     // row weights (padded)
    __shared__ float sT[3][PLANE_T];                  // 3-plane YCbCr tile, 8.2 KB
    __shared__ int   sBp[BX];                         // even-j base per pair
    __shared__ int   sBi[BY];                         // row bases

    const int tx  = threadIdx.x;            // 0..55
    const int ty  = threadIdx.y;            // 0..3
    const int tid = ty * BX + tx;
    const int b   = blockIdx.z;
    const int i0  = blockIdx.x * BY;

    const int rmin = comp_base(i0);

    // ---- per-block weight construction (once for all 3 cq) ----------------
    if (tid < HW) {
        const int j = tid;
        float W[8][3];
        comp_weights(j, W);
        const int bj = comp_base(j);
        if ((j & 1) == 0) sBp[j >> 1] = bj;
        const bool sh = (bj - comp_base(j & ~1)) != 0;   // pair-relative shift
        float* dst = &sW4[(j >> 1) * PSTRIDE + (j & 1) * 4];
        #pragma unroll
        for (int v = 0; v < 8; v++) {
            dst[v * 8 + 0] = sh ? 0.0f    : W[v][0];
            dst[v * 8 + 1] = sh ? W[v][0] : W[v][1];
            dst[v * 8 + 2] = sh ? W[v][1] : W[v][2];
            dst[v * 8 + 3] = sh ? W[v][2] : 0.0f;
        }
    } else if (tid < HW + BY) {
        const int r = tid - HW;
        float W[8][3];
        comp_weights(i0 + r, W);
        #pragma unroll
        for (int u = 0; u < 8; u++) {
            sR[r * 25 + u * 3 + 0] = W[u][0];
            sR[r * 25 + u * 3 + 1] = W[u][1];
            sR[r * 25 + u * 3 + 2] = W[u][2];
        }
        sBi[r] = comp_base(i0 + r);
    }

    // ---- 3-plane YCbCr tile (all threads) ---------------------------------
    {
        const float* xb = x + (size_t)b * 3 * NPLANE;
        for (int e = tid; e < PLANE_T; e += NTHREADS) {
            int lr = e / COLS_T, c = e - lr * COLS_T;
            int srow = rmin + lr; if (srow > HW - 1) srow = HW - 1;
            int scol = c;         if (scol > HW - 1) scol = HW - 1;
            int off = srow * HW + scol;
            float p0 = __ldg(xb + off);
            float p1 = __ldg(xb + NPLANE + off);
            float p2 = __ldg(xb + 2 * NPLANE + off);
            #pragma unroll
            for (int cq = 0; cq < 3; cq++) {
                sT[cq][e] = fmaf(127.5f * c_M[cq][0], p0,
                            fmaf(127.5f * c_M[cq][1], p1,
                                 127.5f * c_M[cq][2] * p2));
            }
        }
    }
    __syncthreads();

    // ---- per-thread work: loop over the 3 cq channels ---------------------
    const int i   = i0 + ty;
    const int j0  = 2 * tx;
    const int bj0 = sBp[tx];
    const int lr  = sBi[ty] - rmin;          // 0..3

    const float* wr = &sR[ty * 25];
    const float* wp = &sW4[tx * PSTRIDE];
    float* outb = out + ((size_t)b * 162) * NPLANE + i * HW + j0;

    #pragma unroll
    for (int cq = 0; cq < 3; cq++) {
        // 3x4 patch
        float t[3][4];
        #pragma unroll
        for (int r = 0; r < 3; r++) {
            const float* row = &sT[cq][(lr + r) * COLS_T + bj0];
            #pragma unroll
            for (int s = 0; s < 4; s++) t[r][s] = row[s];
        }

        // gv[u][s] = sum_r W[i][u][r] * t[r][s]
        float gv[8][4];
        #pragma unroll
        for (int u = 0; u < 8; u++) {
            float w0 = wr[u * 3 + 0], w1 = wr[u * 3 + 1], w2 = wr[u * 3 + 2];
            #pragma unroll
            for (int s = 0; s < 4; s++)
                gv[u][s] = fmaf(w0, t[0][s], fmaf(w1, t[1][s], w2 * t[2][s]));
        }

        // Epilogue: 27 float2 stores; two 4-wide dots per kept (u,v)
        float* outp = outb + (size_t)(cq * 54) * NPLANE;

        #pragma unroll
        for (int v = 0; v < 8; v++) {
            const float4 wa = *reinterpret_cast<const float4*>(wp + v * 8);
            const float4 wb = *reinterpret_cast<const float4*>(wp + v * 8 + 4);
            #pragma unroll
            for (int u = 0; u < 8; u++) {
                const int idx = u * 8 + v;
                if ((SUB_MASK >> idx) & 1ULL) continue;
                const int m = idx - __popcll(SUB_MASK & ((1ULL << idx) - 1ULL));
                float2 val;
                val.x = fmaf(gv[u][0], wa.x, fmaf(gv[u][1], wa.y,
                        fmaf(gv[u][2], wa.z, gv[u][3] * wa.w)));
                val.y = fmaf(gv[u][0], wb.x, fmaf(gv[u][1], wb.y,
                        fmaf(gv[u][2], wb.z, gv[u][3] * wb.w)));
                *reinterpret_cast<float2*>(outp + (size_t)m * NPLANE) = val;
            }
        }
    }
}

// ---------------------------------------------------------------------------
extern "C" void kernel_launch(void* const* d_in, const int* in_sizes, int n_in,
                              void* d_out, int out_size) {
    const float* x = (const float*)d_in[0];   // (16, 3, 112, 112) fp32
    float* out = (float*)d_out;               // (16, 162, 112, 112) fp32

    dim3 block(BX, BY);                       // 224 threads
    dim3 grid(HW / BY, 1, NBATCH);            // (28, 1, 16) = 448 blocks
    dct_main_kernel<<<grid, block>>>(x, out);
}

// round 11
// speedup vs baseline: 2.1304x; 2.1304x over previous
#include <cuda_runtime.h>
#include <math.h>

// ---------------------------------------------------------------------------
// DCTModel collapsed to a single kernel:
//   out[b, cq*54+m(u,v), i, j] =
//     sum_{r,s<3} W[i][u][r] * W[j][v][s] * t[b,cq, base_i+r, base_j+s]
//   t = 127.5 * (RGB2YCBCR @ x);  additive constants only hit the dropped DC.
//
// R10: revert to the R5 shape (grid 1344 = (28 i-groups, 3 cq, 16 b); the R9
// cq-fusion lost 2.2x by starving block-level parallelism and widening the
// concurrent write footprint). Changes vs R5:
//   - tile LDGs issued FIRST into registers; weight-gen ALU overlaps their
//     latency; combine+STS afterwards (R5 serialized weights before loads)
//   - consumers compute base indices arithmetically (sBp/sBi smem removed)
// ---------------------------------------------------------------------------

#define HW 112
#define NPLANE 12544
#define NBATCH 16

#define BX 56           // j-pairs per block
#define BY 4            // i rows per block
#define NTHREADS (BX*BY)
#define ROWS_T 6
#define COLS_T 114
#define PLANE_T (ROWS_T*COLS_T)   // 684
#define NIT ((PLANE_T + NTHREADS - 1) / NTHREADS)  // 4 prefetch iterations
#define PSTRIDE 68      // floats per pair in sW4 (64 data + 4 pad)

__constant__ float c_M[3][3] = {
    { 0.299f,     0.587f,    0.114f    },
    {-0.168736f, -0.331264f, 0.5f      },
    { 0.5f,      -0.418688f, -0.081312f}
};

// SUB_CHANNELS = {0,1,2,3,4,5,8,9,16,24}
#define SUB_MASK 0x000000000101033FULL

// ---------------------------------------------------------------------------
// cos(k*pi/16), constexpr -> folded to FFMA immediates in unrolled loops.
// ---------------------------------------------------------------------------
__host__ __device__ constexpr float cosw(int k) {
    const double T[9] = {
        1.0,
        0.98078528040323044913,
        0.92387953251128675613,
        0.83146961230254523708,
        0.70710678118654752440,
        0.55557023301960222474,
        0.38268343236508977173,
        0.19509032201612826785,
        0.0
    };
    k &= 31;
    if (k > 16) k = 32 - k;
    double s = 1.0;
    if (k > 8) { s = -1.0; k = 16 - k; }
    return (float)(s * T[k]);
}

// base index: src is monotone in x, so base = i0[x=0]
__device__ __forceinline__ int comp_base(int idx) {
    float src = (float)(8 * idx * 111) / 895.0f;
    int f = (int)floorf(src);
    return (f > HW - 2) ? (HW - 2) : f;
}

// Fused (DCT x upsample) weights for one block index: W[v][k], k<3.
__device__ __forceinline__ void comp_weights(int idx, float W[8][3]) {
    const int base = comp_base(idx);
    float A0[8], A1[8], A2[8];
    #pragma unroll
    for (int x = 0; x < 8; x++) {
        float src = (float)((8 * idx + x) * 111) / 895.0f;
        int f = (int)floorf(src);
        if (f > HW - 2) f = HW - 2;
        float w = src - (float)f;
        bool z = (f == base);           // offset 0 or 1
        A0[x] = z ? 1.0f - w : 0.0f;
        A1[x] = z ? w        : 1.0f - w;
        A2[x] = z ? 0.0f     : w;
    }
    #pragma unroll
    for (int v = 0; v < 8; v++) {
        float s0 = 0.f, s1 = 0.f, s2 = 0.f;
        #pragma unroll
        for (int x = 0; x < 8; x++) {
            const float c = cosw((2 * x + 1) * v);   // compile-time immediate
            s0 = fmaf(c, A0[x], s0);
            s1 = fmaf(c, A1[x], s1);
            s2 = fmaf(c, A2[x], s2);
        }
        const float sc = (v == 0) ? 0.35355339059327373f : 0.5f;  // alpha_v/2
        W[v][0] = s0 * sc; W[v][1] = s1 * sc; W[v][2] = s2 * sc;
    }
}

// ---------------------------------------------------------------------------
// Single kernel: block = (56 j-pairs, 4 i-rows); grid = (28, 3 cq, 16 b).
// ---------------------------------------------------------------------------
__global__ __launch_bounds__(NTHREADS, 4)
void dct_main_kernel(const float* __restrict__ x, float* __restrict__ out) {
    __shared__ __align__(16) float sW4[BX * PSTRIDE]; // 15.2 KB
    __shared__ float sR[BY * 25];                     // row weights (padded)
    __shared__ float sT[PLANE_T];                     // YCbCr tile (one cq)

    const int tx  = threadIdx.x;            // 0..55
    const int ty  = threadIdx.y;            // 0..3
    const int tid = ty * BX + tx;
    const int cq  = blockIdx.y;
    const int b   = blockIdx.z;
    const int i0  = blockIdx.x * BY;

    const int rmin = comp_base(i0);

    // ---- phase 1: issue ALL tile LDGs first (latency gets overlapped) -----
    float p0[NIT], p1[NIT], p2[NIT];
    {
        const float* xb = x + (size_t)b * 3 * NPLANE;
        #pragma unroll
        for (int it = 0; it < NIT; it++) {
            int e = tid + it * NTHREADS;
            bool ok = (e < PLANE_T);
            int ec = ok ? e : 0;
            int lr = ec / COLS_T, c = ec - lr * COLS_T;
            int srow = rmin + lr; if (srow > HW - 1) srow = HW - 1;
            int scol = c;         if (scol > HW - 1) scol = HW - 1;
            int off = srow * HW + scol;
            p0[it] = ok ? __ldg(xb + off)              : 0.f;
            p1[it] = ok ? __ldg(xb + NPLANE + off)     : 0.f;
            p2[it] = ok ? __ldg(xb + 2 * NPLANE + off) : 0.f;
        }
    }

    // ---- phase 2: weight construction (ALU overlaps the loads above) ------
    if (tid < HW) {
        const int j = tid;
        float W[8][3];
        comp_weights(j, W);
        const bool sh = (comp_base(j) - comp_base(j & ~1)) != 0;  // pair shift
        float* dst = &sW4[(j >> 1) * PSTRIDE + (j & 1) * 4];
        #pragma unroll
        for (int v = 0; v < 8; v++) {
            dst[v * 8 + 0] = sh ? 0.0f    : W[v][0];
            dst[v * 8 + 1] = sh ? W[v][0] : W[v][1];
            dst[v * 8 + 2] = sh ? W[v][1] : W[v][2];
            dst[v * 8 + 3] = sh ? W[v][2] : 0.0f;
        }
    } else if (tid < HW + BY) {
        const int r = tid - HW;
        float W[8][3];
        comp_weights(i0 + r, W);
        #pragma unroll
        for (int u = 0; u < 8; u++) {
            sR[r * 25 + u * 3 + 0] = W[u][0];
            sR[r * 25 + u * 3 + 1] = W[u][1];
            sR[r * 25 + u * 3 + 2] = W[u][2];
        }
    }

    // ---- phase 3: combine loaded pixels -> YCbCr, store tile --------------
    {
        const float m0 = 127.5f * c_M[cq][0];
        const float m1 = 127.5f * c_M[cq][1];
        const float m2 = 127.5f * c_M[cq][2];
        #pragma unroll
        for (int it = 0; it < NIT; it++) {
            int e = tid + it * NTHREADS;
            if (e < PLANE_T)
                sT[e] = fmaf(m0, p0[it], fmaf(m1, p1[it], m2 * p2[it]));
        }
    }
    __syncthreads();

    // ---- per-thread work --------------------------------------------------
    const int i   = i0 + ty;
    const int j0  = 2 * tx;
    const int bj0 = comp_base(j0);           // arithmetic, no smem round-trip
    const int lr  = comp_base(i) - rmin;     // 0..3

    float t[3][4];
    #pragma unroll
    for (int r = 0; r < 3; r++) {
        const float* row = &sT[(lr + r) * COLS_T + bj0];
        #pragma unroll
        for (int s = 0; s < 4; s++) t[r][s] = row[s];
    }

    // gv[u][s] = sum_r W[i][u][r] * t[r][s]
    float gv[8][4];
    {
        const float* wr = &sR[ty * 25];
        #pragma unroll
        for (int u = 0; u < 8; u++) {
            float w0 = wr[u * 3 + 0], w1 = wr[u * 3 + 1], w2 = wr[u * 3 + 2];
            #pragma unroll
            for (int s = 0; s < 4; s++)
                gv[u][s] = fmaf(w0, t[0][s], fmaf(w1, t[1][s], w2 * t[2][s]));
        }
    }

    // Epilogue: 54 float2 stores; two 4-wide dots per kept (u,v)
    float* outp = out + ((size_t)(b * 162 + cq * 54)) * NPLANE + i * HW + j0;
    const float* wp = &sW4[tx * PSTRIDE];

    #pragma unroll
    for (int v = 0; v < 8; v++) {
        const float4 wa = *reinterpret_cast<const float4*>(wp + v * 8);
        const float4 wb = *reinterpret_cast<const float4*>(wp + v * 8 + 4);
        #pragma unroll
        for (int u = 0; u < 8; u++) {
            const int idx = u * 8 + v;
            if ((SUB_MASK >> idx) & 1ULL) continue;
            const int m = idx - __popcll(SUB_MASK & ((1ULL << idx) - 1ULL));
            float2 val;
            val.x = fmaf(gv[u][0], wa.x, fmaf(gv[u][1], wa.y,
                    fmaf(gv[u][2], wa.z, gv[u][3] * wa.w)));
            val.y = fmaf(gv[u][0], wb.x, fmaf(gv[u][1], wb.y,
                    fmaf(gv[u][2], wb.z, gv[u][3] * wb.w)));
            *reinterpret_cast<float2*>(outp + (size_t)m * NPLANE) = val;
        }
    }
}

// ---------------------------------------------------------------------------
extern "C" void kernel_launch(void* const* d_in, const int* in_sizes, int n_in,
                              void* d_out, int out_size) {
    const float* x = (const float*)d_in[0];   // (16, 3, 112, 112) fp32
    float* out = (float*)d_out;               // (16, 162, 112, 112) fp32

    dim3 block(BX, BY);                       // 224 threads
    dim3 grid(HW / BY, 3, NBATCH);            // (28, 3, 16) = 1344 blocks
    dct_main_kernel<<<grid, block>>>(x, out);
}